// round 1
// baseline (speedup 1.0000x reference)
#include <cuda_runtime.h>

#define NN 4096
#define MM 4096
#define DTC 0.01f

// 64 MB scratch for K = exp(-x). __device__ global (no allocation APIs).
__device__ float g_K[(size_t)NN * MM];

__global__ void exp_kernel(const float* __restrict__ x) {
    size_t p = (size_t)blockIdx.x * blockDim.x + threadIdx.x;
    const float4* x4 = (const float4*)x;
    float4* k4 = (float4*)g_K;
    float4 v = x4[p];
    float4 o;
    o.x = expf(-v.x);
    o.y = expf(-v.y);
    o.z = expf(-v.z);
    o.w = expf(-v.w);
    k4[p] = o;
}

// C[j,i] = sum_{l} h[j-l] * K[l,i]  (h index < 0 -> 0), then epilogue:
// out[j,i] = fe[j] + dt*(0.5*K[0,i]*h[j] - 0.5*K[j,i]*h[0] - C[j,i])
__global__ __launch_bounds__(256, 2) void memint_gemm(
    const float* __restrict__ fe,
    const float* __restrict__ h,
    float* __restrict__ out)
{
    __shared__ float Ks[2][16][128];
    __shared__ float hs[2][144];
    __shared__ float k0s[128];

    const int tid = threadIdx.x;
    const int tx = tid & 15;
    const int ty = tid >> 4;
    const int i0 = blockIdx.x * 128;
    // heavy (large-j) tiles first to shrink the triangular wave tail
    const int j0 = (gridDim.y - 1 - blockIdx.y) * 128;

    if (tid < 128) k0s[tid] = g_K[i0 + tid];

    // l-tiles needed: l0 <= j0+127  ->  lt in [0, j0/16 + 7]
    const int numT = (j0 >> 4) + 8;

    // K-tile load mapping: 16x128 floats = 512 float4, 2 per thread
    const int r0 = tid >> 5;
    const int c0 = (tid & 31) << 2;
    const int r1 = (tid + 256) >> 5;
    const int c1 = c0; // (tid+256)&31 == tid&31

    float acc[8][8];
    #pragma unroll
    for (int r = 0; r < 8; r++)
        #pragma unroll
        for (int c = 0; c < 8; c++) acc[r][c] = 0.f;

    float4 sA, sB;
    float sh = 0.f;

    // preload tile 0
    {
        sA = *(const float4*)&g_K[(size_t)r0 * MM + i0 + c0];
        sB = *(const float4*)&g_K[(size_t)r1 * MM + i0 + c1];
        if (tid < 144) {
            int idx = j0 - 15 + tid;
            sh = (idx >= 0 && idx < NN) ? h[idx] : 0.f;
        }
    }
    *(float4*)&Ks[0][r0][c0] = sA;
    *(float4*)&Ks[0][r1][c1] = sB;
    if (tid < 144) hs[0][tid] = sh;
    __syncthreads();

    for (int t = 0; t < numT; t++) {
        const int cur = t & 1;
        const bool more = (t + 1 < numT);
        if (more) {
            const int l0 = (t + 1) << 4;
            sA = *(const float4*)&g_K[(size_t)(l0 + r0) * MM + i0 + c0];
            sB = *(const float4*)&g_K[(size_t)(l0 + r1) * MM + i0 + c1];
            if (tid < 144) {
                int idx = j0 - l0 - 15 + tid;
                sh = (idx >= 0 && idx < NN) ? h[idx] : 0.f;
            }
        }
        #pragma unroll
        for (int ll = 0; ll < 16; ll++) {
            float a[8], b[8];
            const int hb = ty + 15 - ll;
            #pragma unroll
            for (int r = 0; r < 8; r++) a[r] = hs[cur][hb + (r << 4)];
            float4 b0 = *(const float4*)&Ks[cur][ll][tx << 2];
            float4 b1 = *(const float4*)&Ks[cur][ll][64 + (tx << 2)];
            b[0] = b0.x; b[1] = b0.y; b[2] = b0.z; b[3] = b0.w;
            b[4] = b1.x; b[5] = b1.y; b[6] = b1.z; b[7] = b1.w;
            #pragma unroll
            for (int r = 0; r < 8; r++)
                #pragma unroll
                for (int c = 0; c < 8; c++)
                    acc[r][c] += a[r] * b[c];
        }
        if (more) {
            const int nxt = cur ^ 1;
            *(float4*)&Ks[nxt][r0][c0] = sA;
            *(float4*)&Ks[nxt][r1][c1] = sB;
            if (tid < 144) hs[nxt][tid] = sh;
        }
        __syncthreads();
    }

    // epilogue
    const float h0 = __ldg(&h[0]);
    #pragma unroll
    for (int r = 0; r < 8; r++) {
        const int j = j0 + ty + (r << 4);
        const float fej = __ldg(&fe[j]);
        const float hj = __ldg(&h[j]);
        #pragma unroll
        for (int g = 0; g < 2; g++) {
            const int ic = (g << 6) + (tx << 2);
            const int i = i0 + ic;
            float4 kj = *(const float4*)&g_K[(size_t)j * MM + i];
            float4 o;
            o.x = fej + DTC * (0.5f * k0s[ic + 0] * hj - 0.5f * kj.x * h0 - acc[r][(g << 2) + 0]);
            o.y = fej + DTC * (0.5f * k0s[ic + 1] * hj - 0.5f * kj.y * h0 - acc[r][(g << 2) + 1]);
            o.z = fej + DTC * (0.5f * k0s[ic + 2] * hj - 0.5f * kj.z * h0 - acc[r][(g << 2) + 2]);
            o.w = fej + DTC * (0.5f * k0s[ic + 3] * hj - 0.5f * kj.w * h0 - acc[r][(g << 2) + 3]);
            *(float4*)&out[(size_t)j * MM + i] = o;
        }
    }
}

extern "C" void kernel_launch(void* const* d_in, const int* in_sizes, int n_in,
                              void* d_out, int out_size) {
    const float* x  = (const float*)d_in[0];
    const float* fe = (const float*)d_in[1];
    const float* h  = (const float*)d_in[2];
    float* out = (float*)d_out;

    // K = exp(-x): 16M elems, float4-vectorized
    exp_kernel<<<((size_t)NN * MM) / 4 / 256, 256>>>(x);

    dim3 grid(MM / 128, NN / 128);
    memint_gemm<<<grid, 256>>>(fe, h, out);
}

// round 3
// speedup vs baseline: 2.5801x; 2.5801x over previous
#include <cuda_runtime.h>
#include <cuda_bf16.h>
#include <cstdint>

#define NN 4096
#define MM 4096
#define DTC 0.01f

// bf16 split of K = exp(-x): K ~= K1 + K2
__device__ __nv_bfloat16 g_K1[(size_t)NN * MM];
__device__ __nv_bfloat16 g_K2[(size_t)NN * MM];

__global__ void exp_kernel(const float* __restrict__ x) {
    size_t p = (size_t)blockIdx.x * blockDim.x + threadIdx.x;
    float4 v = ((const float4*)x)[p];
    float k[4] = {expf(-v.x), expf(-v.y), expf(-v.z), expf(-v.w)};
    uint32_t w1[2], w2[2];
    #pragma unroll
    for (int q = 0; q < 2; q++) {
        __nv_bfloat16 a0 = __float2bfloat16(k[2*q]);
        __nv_bfloat16 a1 = __float2bfloat16(k[2*q+1]);
        __nv_bfloat16 b0 = __float2bfloat16(k[2*q]   - __bfloat162float(a0));
        __nv_bfloat16 b1 = __float2bfloat16(k[2*q+1] - __bfloat162float(a1));
        w1[q] = ((uint32_t)__bfloat16_as_ushort(a1) << 16) | __bfloat16_as_ushort(a0);
        w2[q] = ((uint32_t)__bfloat16_as_ushort(b1) << 16) | __bfloat16_as_ushort(b0);
    }
    ((uint2*)g_K1)[p] = make_uint2(w1[0], w1[1]);
    ((uint2*)g_K2)[p] = make_uint2(w2[0], w2[1]);
}

// ---------------- smem layout (bytes) ----------------
// hr32_1 / hr32_2: reversed, pair-packed h splits: (NN+128) uint32 each
#define SM_HR1   0
#define SM_HR2   16896
#define SM_STAGE 33792
// stage: A1[128][40]h (10240B), A2 (10240B), B1[32][136]h (8704B), B2 (8704B)
#define ST_A1 0
#define ST_A2 10240
#define ST_B1 20480
#define ST_B2 29184
#define STAGE_BYTES 37888
#define SMEM_TOTAL (SM_STAGE + 2 * STAGE_BYTES)   // 109568

#define A_STRIDE_B 80     // bytes per A row (32 halfs + pad)
#define B_STRIDE_B 272    // bytes per B row (128 halfs + pad)

__device__ __forceinline__ uint32_t smem_u32(const void* p) {
    return (uint32_t)__cvta_generic_to_shared(p);
}
__device__ __forceinline__ void cp16(uint32_t dst, const void* src) {
    asm volatile("cp.async.cg.shared.global [%0], [%1], 16;" :: "r"(dst), "l"(src) : "memory");
}
#define CP_COMMIT() asm volatile("cp.async.commit_group;" ::: "memory")
#define CP_WAIT0()  asm volatile("cp.async.wait_group 0;" ::: "memory")

__device__ __forceinline__ void ldmat_x4(uint32_t* r, uint32_t addr) {
    asm volatile("ldmatrix.sync.aligned.m8n8.x4.shared.b16 {%0,%1,%2,%3}, [%4];"
                 : "=r"(r[0]), "=r"(r[1]), "=r"(r[2]), "=r"(r[3]) : "r"(addr));
}
__device__ __forceinline__ void ldmat_x4_t(uint32_t* r, uint32_t addr) {
    asm volatile("ldmatrix.sync.aligned.m8n8.x4.trans.shared.b16 {%0,%1,%2,%3}, [%4];"
                 : "=r"(r[0]), "=r"(r[1]), "=r"(r[2]), "=r"(r[3]) : "r"(addr));
}
__device__ __forceinline__ void mma16816(float* c, const uint32_t* a, const uint32_t* b) {
    asm volatile("mma.sync.aligned.m16n8k16.row.col.f32.bf16.bf16.f32 "
                 "{%0,%1,%2,%3}, {%4,%5,%6,%7}, {%8,%9}, {%0,%1,%2,%3};"
                 : "+f"(c[0]), "+f"(c[1]), "+f"(c[2]), "+f"(c[3])
                 : "r"(a[0]), "r"(a[1]), "r"(a[2]), "r"(a[3]), "r"(b[0]), "r"(b[1]));
}

// CTA tile: 128(j) x 128(i). 8 warps: wy=wid&3 (j, 32 each), wx=wid>>2 (i, 64 each).
// Warp tile 32x64 = 2 m16 x 8 n8. K-chunk = 32 (2 k16 steps). 3 bf16 passes.
__global__ __launch_bounds__(256) void memint_mma(
    const float* __restrict__ fe,
    const float* __restrict__ h,
    float* __restrict__ out)
{
    extern __shared__ char smem[];
    const uint32_t sbase = smem_u32(smem);
    const int tid  = threadIdx.x;
    const int lane = tid & 31;
    const int wid  = tid >> 5;
    const int wy   = wid & 3;
    const int wx   = wid >> 2;
    const int i0 = blockIdx.x * 128;
    const int j0 = ((int)gridDim.y - 1 - (int)blockIdx.y) * 128;   // heavy tiles first

    uint32_t* hr1 = (uint32_t*)(smem + SM_HR1);
    uint32_t* hr2 = (uint32_t*)(smem + SM_HR2);

    // Build reversed pair-packed h splits:
    // hr[v] = h[NN-1-v] (0 if OOB). hrX[v] packs (hr[v], hr[v+1]) as bf16 lo/hi.
    for (int v = tid; v < NN + 128; v += 256) {
        float e0 = (v < NN)     ? h[NN - 1 - v] : 0.f;
        float e1 = (v + 1 < NN) ? h[NN - 2 - v] : 0.f;
        __nv_bfloat16 a0 = __float2bfloat16(e0);
        __nv_bfloat16 a1 = __float2bfloat16(e1);
        __nv_bfloat16 b0 = __float2bfloat16(e0 - __bfloat162float(a0));
        __nv_bfloat16 b1 = __float2bfloat16(e1 - __bfloat162float(a1));
        hr1[v] = ((uint32_t)__bfloat16_as_ushort(a1) << 16) | __bfloat16_as_ushort(a0);
        hr2[v] = ((uint32_t)__bfloat16_as_ushort(b1) << 16) | __bfloat16_as_ushort(b0);
    }
    __syncthreads();

    const int numT = (j0 >> 5) + 4;

    // ---- producers ----
    auto issue_B = [&](int t) {
        const int l0 = t * 32;
        const uint32_t bs = sbase + SM_STAGE + (uint32_t)(t & 1) * STAGE_BYTES;
        #pragma unroll
        for (int k = 0; k < 4; k++) {
            int m = tid + k * 256;              // 0..1023: 16B segments
            int split = m >> 9;                 // 0: K1, 1: K2
            int mm = m & 511;
            int row = mm >> 4;                  // l row 0..31
            int seg = mm & 15;                  // 16B seg in 256B row
            uint32_t dst = bs + (uint32_t)(split ? ST_B2 : ST_B1)
                         + (uint32_t)row * B_STRIDE_B + (uint32_t)seg * 16;
            const __nv_bfloat16* src = (split ? g_K2 : g_K1)
                         + (size_t)(l0 + row) * MM + i0 + seg * 8;
            cp16(dst, src);
        }
        CP_COMMIT();
    };

    auto gen_A = [&](int t) {
        const int l0 = t * 32;
        char* as = smem + SM_STAGE + (size_t)(t & 1) * STAGE_BYTES;
        const int j    = tid & 127;
        const int half = tid >> 7;              // 0: l pairs 0-7, 1: pairs 8-15
        const int vb   = NN - 1 - (j0 + j) + l0 + half * 16;
        uint32_t* a1 = (uint32_t*)(as + ST_A1 + (size_t)j * A_STRIDE_B + half * 32);
        uint32_t* a2 = (uint32_t*)(as + ST_A2 + (size_t)j * A_STRIDE_B + half * 32);
        #pragma unroll
        for (int p = 0; p < 8; p++) {
            a1[p] = hr1[vb + 2 * p];
            a2[p] = hr2[vb + 2 * p];
        }
    };

    issue_B(0);
    gen_A(0);

    float c[16][4];
    #pragma unroll
    for (int f = 0; f < 16; f++)
        #pragma unroll
        for (int q = 0; q < 4; q++) c[f][q] = 0.f;

    // per-lane ldmatrix base offsets
    const uint32_t a_row = (uint32_t)(wy * 32 + (lane & 15)) * A_STRIDE_B
                         + (uint32_t)(lane >> 4) * 16;
    const uint32_t b_row = (uint32_t)((lane & 7) + ((lane >> 3) & 1) * 8) * B_STRIDE_B
                         + (uint32_t)(wx * 64 + (lane >> 4) * 8) * 2;

    for (int t = 0; t < numT; t++) {
        CP_WAIT0();
        __syncthreads();
        if (t + 1 < numT) { issue_B(t + 1); gen_A(t + 1); }

        const uint32_t st = sbase + SM_STAGE + (uint32_t)(t & 1) * STAGE_BYTES;
        #pragma unroll
        for (int ks = 0; ks < 2; ks++) {
            uint32_t A1f[2][4], A2f[2][4], B1f[4][4], B2f[4][4];
            #pragma unroll
            for (int mt = 0; mt < 2; mt++) {
                uint32_t ar = st + a_row + (uint32_t)mt * (16 * A_STRIDE_B) + (uint32_t)ks * 32;
                ldmat_x4(A1f[mt], ar + ST_A1);
                ldmat_x4(A2f[mt], ar + ST_A2);
            }
            #pragma unroll
            for (int np = 0; np < 4; np++) {
                uint32_t br = st + b_row + (uint32_t)ks * (16 * B_STRIDE_B) + (uint32_t)np * 32;
                ldmat_x4_t(B1f[np], br + ST_B1);
                ldmat_x4_t(B2f[np], br + ST_B2);
            }
            #pragma unroll
            for (int mt = 0; mt < 2; mt++)
                #pragma unroll
                for (int nt = 0; nt < 8; nt++) {
                    float* cc = c[mt * 8 + nt];
                    const uint32_t* b1 = &B1f[nt >> 1][(nt & 1) * 2];
                    const uint32_t* b2 = &B2f[nt >> 1][(nt & 1) * 2];
                    mma16816(cc, A1f[mt], b1);   // h1*k1
                    mma16816(cc, A1f[mt], b2);   // h1*k2
                    mma16816(cc, A2f[mt], b1);   // h2*k1
                }
        }
    }

    // ---- epilogue ----
    __syncthreads();
    float* k0s = (float*)(smem + SM_STAGE);
    float* fes = k0s + 128;
    float* hjs = fes + 128;
    if (tid < 128) {
        k0s[tid] = __bfloat162float(g_K1[i0 + tid]) + __bfloat162float(g_K2[i0 + tid]);
        fes[tid] = fe[j0 + tid];
        hjs[tid] = h[j0 + tid];
    }
    __syncthreads();

    const float h0 = __ldg(&h[0]);
    const int gq = lane >> 2;
    const int tq = lane & 3;

    #pragma unroll
    for (int mt = 0; mt < 2; mt++) {
        #pragma unroll
        for (int half = 0; half < 2; half++) {
            const int jl = wy * 32 + mt * 16 + gq + half * 8;
            const int j  = j0 + jl;
            const float fej = fes[jl];
            const float hj  = hjs[jl];
            #pragma unroll
            for (int nt = 0; nt < 8; nt++) {
                const int il = wx * 64 + nt * 8 + tq * 2;
                const int i  = i0 + il;
                const size_t gi = (size_t)j * MM + i;
                __nv_bfloat162 p1 = *(const __nv_bfloat162*)&g_K1[gi];
                __nv_bfloat162 p2 = *(const __nv_bfloat162*)&g_K2[gi];
                float kj0 = __bfloat162float(p1.x) + __bfloat162float(p2.x);
                float kj1 = __bfloat162float(p1.y) + __bfloat162float(p2.y);
                const float* cc = c[mt * 8 + nt];
                float2 o;
                o.x = fej + DTC * (0.5f * k0s[il]     * hj - 0.5f * kj0 * h0 - cc[half * 2 + 0]);
                o.y = fej + DTC * (0.5f * k0s[il + 1] * hj - 0.5f * kj1 * h0 - cc[half * 2 + 1]);
                *(float2*)&out[gi] = o;
            }
        }
    }
}

extern "C" void kernel_launch(void* const* d_in, const int* in_sizes, int n_in,
                              void* d_out, int out_size) {
    const float* x  = (const float*)d_in[0];
    const float* fe = (const float*)d_in[1];
    const float* h  = (const float*)d_in[2];
    float* out = (float*)d_out;

    cudaFuncSetAttribute(memint_mma, cudaFuncAttributeMaxDynamicSharedMemorySize, SMEM_TOTAL);

    exp_kernel<<<((size_t)NN * MM) / 4 / 256, 256>>>(x);

    dim3 grid(MM / 128, NN / 128);
    memint_mma<<<grid, 256, SMEM_TOTAL>>>(fe, h, out);
}

// round 5
// speedup vs baseline: 5.9630x; 2.3111x over previous
#include <cuda_runtime.h>
#include <cuda_fp16.h>
#include <cstdint>

#define NN 4096
#define MM 4096
#define DTC 0.01f

__device__ __half g_Kh[(size_t)NN * MM];

__global__ void exp_kernel(const float* __restrict__ x) {
    size_t p = (size_t)blockIdx.x * blockDim.x + threadIdx.x;
    float4 v = ((const float4*)x)[p];
    __half2 a = __floats2half2_rn(expf(-v.x), expf(-v.y));
    __half2 b = __floats2half2_rn(expf(-v.z), expf(-v.w));
    uint2 w;
    w.x = *(uint32_t*)&a;
    w.y = *(uint32_t*)&b;
    ((uint2*)g_Kh)[p] = w;
}

// ---------------- smem layout ----------------
#define HR_WORDS (NN + 160)
#define SM_B_OFF (HR_WORDS * 4)        // 17024 bytes
#define B_STRIDE 272                   // 128 halfs + 8 pad
#define STAGE_B  (32 * B_STRIDE)       // 8704
#define NSTAGE   4
#define SMEM_TOTAL (SM_B_OFF + NSTAGE * STAGE_B)   // 51840

__device__ __forceinline__ uint32_t smem_u32(const void* p) {
    return (uint32_t)__cvta_generic_to_shared(p);
}
__device__ __forceinline__ void cp16(uint32_t dst, const void* src) {
    asm volatile("cp.async.cg.shared.global [%0], [%1], 16;" :: "r"(dst), "l"(src) : "memory");
}
#define CP_COMMIT() asm volatile("cp.async.commit_group;" ::: "memory")
#define CP_WAIT2()  asm volatile("cp.async.wait_group 2;" ::: "memory")

__device__ __forceinline__ void ldmat_x4_t(uint32_t* r, uint32_t addr) {
    asm volatile("ldmatrix.sync.aligned.m8n8.x4.trans.shared.b16 {%0,%1,%2,%3}, [%4];"
                 : "=r"(r[0]), "=r"(r[1]), "=r"(r[2]), "=r"(r[3]) : "r"(addr));
}
__device__ __forceinline__ void mma16816(float* c, const uint32_t* a, const uint32_t* b) {
    asm volatile("mma.sync.aligned.m16n8k16.row.col.f32.f16.f16.f32 "
                 "{%0,%1,%2,%3}, {%4,%5,%6,%7}, {%8,%9}, {%0,%1,%2,%3};"
                 : "+f"(c[0]), "+f"(c[1]), "+f"(c[2]), "+f"(c[3])
                 : "r"(a[0]), "r"(a[1]), "r"(a[2]), "r"(a[3]), "r"(b[0]), "r"(b[1]));
}

// CTA tile 128(j) x 128(i), 4 warps of 64x64. K-chunk 32 (2 x k16).
// A fragments generated directly from the reversed pair-packed h table in smem.
__global__ __launch_bounds__(128) void memint_mma(
    const float* __restrict__ fe,
    const float* __restrict__ h,
    float* __restrict__ out)
{
    extern __shared__ char smem[];
    const uint32_t sbase = smem_u32(smem);
    uint32_t* hr = (uint32_t*)smem;

    const int tid  = threadIdx.x;
    const int lane = tid & 31;
    const int wid  = tid >> 5;
    const int wy   = wid & 1;       // j half (64)
    const int wx   = wid >> 1;      // i half (64)
    const int i0 = blockIdx.x * 128;
    const int j0 = ((int)gridDim.y - 1 - (int)blockIdx.y) * 128;   // heavy tiles first

    // hr[v] = (h[NN-1-v], h[NN-2-v]) as half2; zero-padded past the end (causal mask)
    for (int v = tid; v < HR_WORDS; v += 128) {
        float e0 = (v < NN)     ? h[NN - 1 - v] : 0.f;
        float e1 = (v + 1 < NN) ? h[NN - 2 - v] : 0.f;
        __half2 p = __floats2half2_rn(e0, e1);
        hr[v] = *(uint32_t*)&p;
    }
    __syncthreads();

    const int numT = (j0 >> 5) + 4;

    auto issue_B = [&](int t) {
        const int l0 = t * 32;
        const uint32_t bs = sbase + SM_B_OFF + (uint32_t)(t & 3) * STAGE_B;
        #pragma unroll
        for (int k = 0; k < 4; k++) {
            int m = tid + k * 128;       // 512 16B segments
            int row = m >> 4;            // l row 0..31
            int seg = m & 15;
            cp16(bs + (uint32_t)(row * B_STRIDE + seg * 16),
                 &g_Kh[(size_t)(l0 + row) * MM + i0 + seg * 8]);
        }
        CP_COMMIT();
    };

    for (int s = 0; s < 3; s++) { if (s < numT) issue_B(s); else CP_COMMIT(); }

    float c[4][8][4];
    #pragma unroll
    for (int mt = 0; mt < 4; mt++)
        #pragma unroll
        for (int nt = 0; nt < 8; nt++)
            #pragma unroll
            for (int q = 0; q < 4; q++) c[mt][nt][q] = 0.f;

    const uint32_t b_row = (uint32_t)((lane & 7) + ((lane >> 3) & 1) * 8) * B_STRIDE
                         + (uint32_t)(wx * 64 + (lane >> 4) * 8) * 2;
    const int vbase0 = NN - 1 - (j0 + wy * 64 + (lane >> 2)) + 2 * (lane & 3);

    for (int t = 0; t < numT; t++) {
        CP_WAIT2();
        __syncthreads();
        if (t + 3 < numT) issue_B(t + 3); else CP_COMMIT();

        // A words: per mt, 5 hr words cover both k16 steps (a3 = a0 aliasing)
        uint32_t lv[4][5];
        const int vb = vbase0 + t * 32;
        #pragma unroll
        for (int mt = 0; mt < 4; mt++)
            #pragma unroll
            for (int q = 0; q < 5; q++)
                lv[mt][q] = hr[vb - mt * 16 - 8 + 8 * q];

        const uint32_t bs = sbase + SM_B_OFF + (uint32_t)(t & 3) * STAGE_B + b_row;
        #pragma unroll
        for (int ks = 0; ks < 2; ks++) {
            uint32_t Bf[4][4];
            #pragma unroll
            for (int np = 0; np < 4; np++)
                ldmat_x4_t(Bf[np], bs + (uint32_t)(ks * 16 * B_STRIDE + np * 32));
            #pragma unroll
            for (int mt = 0; mt < 4; mt++) {
                uint32_t a[4];
                if (ks == 0) { a[0] = lv[mt][1]; a[1] = lv[mt][0]; a[2] = lv[mt][2]; a[3] = lv[mt][1]; }
                else         { a[0] = lv[mt][3]; a[1] = lv[mt][2]; a[2] = lv[mt][4]; a[3] = lv[mt][3]; }
                #pragma unroll
                for (int nt = 0; nt < 8; nt++)
                    mma16816(c[mt][nt], a, &Bf[nt >> 1][(nt & 1) * 2]);
            }
        }
    }

    // ---- epilogue ----
    const float h0 = __ldg(&h[0]);
    #pragma unroll
    for (int mt = 0; mt < 4; mt++) {
        #pragma unroll
        for (int hf = 0; hf < 2; hf++) {
            const int j = j0 + wy * 64 + mt * 16 + (lane >> 2) + hf * 8;
            const float fej = __ldg(&fe[j]);
            const float hj  = __ldg(&h[j]);
            #pragma unroll
            for (int nt = 0; nt < 8; nt++) {
                const int i = i0 + wx * 64 + nt * 8 + (lane & 3) * 2;
                const size_t gi = (size_t)j * MM + i;
                __half2 kj = *(const __half2*)&g_Kh[gi];
                __half2 k0 = *(const __half2*)&g_Kh[i];
                const float* cc = c[mt][nt];
                float2 o;
                o.x = fej + DTC * (0.5f * __low2float(k0)  * hj - 0.5f * __low2float(kj)  * h0 - cc[hf * 2 + 0]);
                o.y = fej + DTC * (0.5f * __high2float(k0) * hj - 0.5f * __high2float(kj) * h0 - cc[hf * 2 + 1]);
                *(float2*)&out[gi] = o;
            }
        }
    }
}

extern "C" void kernel_launch(void* const* d_in, const int* in_sizes, int n_in,
                              void* d_out, int out_size) {
    const float* x  = (const float*)d_in[0];
    const float* fe = (const float*)d_in[1];
    const float* h  = (const float*)d_in[2];
    float* out = (float*)d_out;

    cudaFuncSetAttribute(memint_mma, cudaFuncAttributeMaxDynamicSharedMemorySize, SMEM_TOTAL);

    exp_kernel<<<((size_t)NN * MM) / 4 / 256, 256>>>(x);

    dim3 grid(MM / 128, NN / 128);
    memint_mma<<<grid, 128, SMEM_TOTAL>>>(fe, h, out);
}

// round 6
// speedup vs baseline: 6.4807x; 1.0868x over previous
#include <cuda_runtime.h>
#include <cuda_fp16.h>
#include <cstdint>

#define NN 4096
#define MM 4096
#define DTC 0.01f

__device__ __half g_Kh[(size_t)NN * MM];

__global__ void exp_kernel(const float* __restrict__ x) {
    size_t p = (size_t)blockIdx.x * blockDim.x + threadIdx.x;
    float4 v = ((const float4*)x)[p];
    __half2 a = __floats2half2_rn(expf(-v.x), expf(-v.y));
    __half2 b = __floats2half2_rn(expf(-v.z), expf(-v.w));
    uint2 w;
    w.x = *(uint32_t*)&a;
    w.y = *(uint32_t*)&b;
    ((uint2*)g_Kh)[p] = w;
}

// ---------------- smem layout ----------------
#define HR_WORDS (NN + 256)
#define SM_B_OFF (HR_WORDS * 4)        // 17408 bytes
#define B_STRIDE 272                   // 128 halfs + 8 pad
#define KC 64                          // K-chunk
#define STAGE_B  (KC * B_STRIDE)       // 17408
#define NSTAGE   3
#define SMEM_TOTAL (SM_B_OFF + NSTAGE * STAGE_B)   // 69632

__device__ __forceinline__ uint32_t smem_u32(const void* p) {
    return (uint32_t)__cvta_generic_to_shared(p);
}
__device__ __forceinline__ void cp16(uint32_t dst, const void* src) {
    asm volatile("cp.async.cg.shared.global [%0], [%1], 16;" :: "r"(dst), "l"(src) : "memory");
}
#define CP_COMMIT() asm volatile("cp.async.commit_group;" ::: "memory")
#define CP_WAIT1()  asm volatile("cp.async.wait_group 1;" ::: "memory")

__device__ __forceinline__ void ldmat_x4_t(uint32_t* r, uint32_t addr) {
    asm volatile("ldmatrix.sync.aligned.m8n8.x4.trans.shared.b16 {%0,%1,%2,%3}, [%4];"
                 : "=r"(r[0]), "=r"(r[1]), "=r"(r[2]), "=r"(r[3]) : "r"(addr));
}
__device__ __forceinline__ void mma16816(float* c, const uint32_t* a, const uint32_t* b) {
    asm volatile("mma.sync.aligned.m16n8k16.row.col.f32.f16.f16.f32 "
                 "{%0,%1,%2,%3}, {%4,%5,%6,%7}, {%8,%9}, {%0,%1,%2,%3};"
                 : "+f"(c[0]), "+f"(c[1]), "+f"(c[2]), "+f"(c[3])
                 : "r"(a[0]), "r"(a[1]), "r"(a[2]), "r"(a[3]), "r"(b[0]), "r"(b[1]));
}

// CTA tile 128(j) x 128(i), 4 warps of 64x64. K-chunk 64 (4 x k16).
// A fragments pulled directly from the reversed pair-packed h table (15 shared words/chunk).
__global__ __launch_bounds__(128) void memint_mma(
    const float* __restrict__ fe,
    const float* __restrict__ h,
    float* __restrict__ out)
{
    extern __shared__ char smem[];
    const uint32_t sbase = smem_u32(smem);
    uint32_t* hr = (uint32_t*)smem;

    const int tid  = threadIdx.x;
    const int lane = tid & 31;
    const int wid  = tid >> 5;
    const int wy   = wid & 1;       // j half (64)
    const int wx   = wid >> 1;      // i half (64)
    const int i0 = blockIdx.x * 128;
    const int j0 = ((int)gridDim.y - 1 - (int)blockIdx.y) * 128;   // heavy tiles first

    // hr[v] = (h[NN-1-v], h[NN-2-v]) as half2; zero-padded past the end (causal mask)
    for (int v = tid; v < HR_WORDS; v += 128) {
        float e0 = (v < NN)     ? h[NN - 1 - v] : 0.f;
        float e1 = (v + 1 < NN) ? h[NN - 2 - v] : 0.f;
        __half2 p = __floats2half2_rn(e0, e1);
        hr[v] = *(uint32_t*)&p;
    }
    __syncthreads();

    const int numT = (j0 >> 6) + 2;

    auto issue_B = [&](int t) {
        const int l0 = t * KC;
        const uint32_t bs = sbase + SM_B_OFF + (uint32_t)(t % 3) * STAGE_B;
        #pragma unroll
        for (int k = 0; k < 8; k++) {
            int m = tid + k * 128;       // 1024 16B segments
            int row = m >> 4;            // l row 0..63
            int seg = m & 15;
            cp16(bs + (uint32_t)(row * B_STRIDE + seg * 16),
                 &g_Kh[(size_t)(l0 + row) * MM + i0 + seg * 8]);
        }
        CP_COMMIT();
    };

    issue_B(0);
    if (numT > 1) issue_B(1); else CP_COMMIT();

    float c[4][8][4];
    #pragma unroll
    for (int mt = 0; mt < 4; mt++)
        #pragma unroll
        for (int nt = 0; nt < 8; nt++)
            #pragma unroll
            for (int q = 0; q < 4; q++) c[mt][nt][q] = 0.f;

    const uint32_t b_row = (uint32_t)((lane & 7) + ((lane >> 3) & 1) * 8) * B_STRIDE
                         + (uint32_t)(wx * 64 + (lane >> 4) * 8) * 2;
    // lv[mt][q] = hr[vb - mt*16 - 8 + 8q] = w[q + 6 - 2*mt], w[s] = hr[vb - 56 + 8s]
    const int wbase0 = NN - 1 - (j0 + wy * 64 + (lane >> 2)) + 2 * (lane & 3) - 56;

    for (int t = 0; t < numT; t++) {
        CP_WAIT1();
        __syncthreads();
        if (t + 2 < numT) issue_B(t + 2); else CP_COMMIT();

        uint32_t w[15];
        const int wb = wbase0 + t * KC;
        #pragma unroll
        for (int s = 0; s < 15; s++) w[s] = hr[wb + 8 * s];

        const uint32_t bs = sbase + SM_B_OFF + (uint32_t)(t % 3) * STAGE_B + b_row;
        #pragma unroll
        for (int ks = 0; ks < 4; ks++) {
            uint32_t Bf[4][4];
            #pragma unroll
            for (int np = 0; np < 4; np++)
                ldmat_x4_t(Bf[np], bs + (uint32_t)(ks * 16 * B_STRIDE + np * 32));
            #pragma unroll
            for (int mt = 0; mt < 4; mt++) {
                // lv[mt][2ks+d] = w[2ks + d + 6 - 2mt]
                const int base = 2 * ks + 6 - 2 * mt;
                uint32_t a[4];
                a[0] = w[base + 1]; a[1] = w[base]; a[2] = w[base + 2]; a[3] = w[base + 1];
                #pragma unroll
                for (int nt = 0; nt < 8; nt++)
                    mma16816(c[mt][nt], a, &Bf[nt >> 1][(nt & 1) * 2]);
            }
        }
    }

    // ---- epilogue ----
    const float h0 = __ldg(&h[0]);
    float k0lo[8], k0hi[8];
    #pragma unroll
    for (int nt = 0; nt < 8; nt++) {
        const int i = i0 + wx * 64 + nt * 8 + (lane & 3) * 2;
        __half2 k0 = *(const __half2*)&g_Kh[i];
        k0lo[nt] = __low2float(k0);
        k0hi[nt] = __high2float(k0);
    }
    #pragma unroll
    for (int mt = 0; mt < 4; mt++) {
        #pragma unroll
        for (int hf = 0; hf < 2; hf++) {
            const int j = j0 + wy * 64 + mt * 16 + (lane >> 2) + hf * 8;
            const float fej = __ldg(&fe[j]);
            const float hj  = __ldg(&h[j]);
            #pragma unroll
            for (int nt = 0; nt < 8; nt++) {
                const int i = i0 + wx * 64 + nt * 8 + (lane & 3) * 2;
                const size_t gi = (size_t)j * MM + i;
                __half2 kj = *(const __half2*)&g_Kh[gi];
                const float* cc = c[mt][nt];
                float2 o;
                o.x = fej + DTC * (0.5f * k0lo[nt] * hj - 0.5f * __low2float(kj)  * h0 - cc[hf * 2 + 0]);
                o.y = fej + DTC * (0.5f * k0hi[nt] * hj - 0.5f * __high2float(kj) * h0 - cc[hf * 2 + 1]);
                *(float2*)&out[gi] = o;
            }
        }
    }
}

extern "C" void kernel_launch(void* const* d_in, const int* in_sizes, int n_in,
                              void* d_out, int out_size) {
    const float* x  = (const float*)d_in[0];
    const float* fe = (const float*)d_in[1];
    const float* h  = (const float*)d_in[2];
    float* out = (float*)d_out;

    cudaFuncSetAttribute(memint_mma, cudaFuncAttributeMaxDynamicSharedMemorySize, SMEM_TOTAL);

    exp_kernel<<<((size_t)NN * MM) / 4 / 256, 256>>>(x);

    dim3 grid(MM / 128, NN / 128);
    memint_mma<<<grid, 128, SMEM_TOTAL>>>(fe, h, out);
}

// round 9
// speedup vs baseline: 6.8818x; 1.0619x over previous
#include <cuda_runtime.h>
#include <cuda_fp16.h>
#include <cstdint>

#define NN 4096
#define MM 4096
#define DTC 0.01f

__device__ __half g_Kh[(size_t)NN * MM];

__global__ void exp_kernel(const float* __restrict__ x) {
    size_t p = (size_t)blockIdx.x * blockDim.x + threadIdx.x;
    float4 v = ((const float4*)x)[p];
    __half2 a = __floats2half2_rn(expf(-v.x), expf(-v.y));
    __half2 b = __floats2half2_rn(expf(-v.z), expf(-v.w));
    uint2 w;
    w.x = *(uint32_t*)&a;
    w.y = *(uint32_t*)&b;
    ((uint2*)g_Kh)[p] = w;
}

// ---------------- smem layout ----------------
#define HR_WORDS (NN + 256)
#define SM_B_OFF (HR_WORDS * 4)        // 17408 bytes
#define B_STRIDE 272                   // 128 halfs + 8 pad
#define KC 64                          // K-chunk
#define STAGE_B  (KC * B_STRIDE)       // 17408
#define NSTAGE   3
#define SMEM_TOTAL (SM_B_OFF + NSTAGE * STAGE_B)   // 69632

__device__ __forceinline__ uint32_t smem_u32(const void* p) {
    return (uint32_t)__cvta_generic_to_shared(p);
}
__device__ __forceinline__ void cp16(uint32_t dst, const void* src) {
    asm volatile("cp.async.cg.shared.global [%0], [%1], 16;" :: "r"(dst), "l"(src) : "memory");
}
#define CP_COMMIT() asm volatile("cp.async.commit_group;" ::: "memory")
#define CP_WAIT1()  asm volatile("cp.async.wait_group 1;" ::: "memory")

__device__ __forceinline__ void ldmat_x4_t(uint32_t* r, uint32_t addr) {
    asm volatile("ldmatrix.sync.aligned.m8n8.x4.trans.shared.b16 {%0,%1,%2,%3}, [%4];"
                 : "=r"(r[0]), "=r"(r[1]), "=r"(r[2]), "=r"(r[3]) : "r"(addr));
}
__device__ __forceinline__ void mma16816(float* c, const uint32_t* a, const uint32_t* b) {
    asm volatile("mma.sync.aligned.m16n8k16.row.col.f32.f16.f16.f32 "
                 "{%0,%1,%2,%3}, {%4,%5,%6,%7}, {%8,%9}, {%0,%1,%2,%3};"
                 : "+f"(c[0]), "+f"(c[1]), "+f"(c[2]), "+f"(c[3])
                 : "r"(a[0]), "r"(a[1]), "r"(a[2]), "r"(a[3]), "r"(b[0]), "r"(b[1]));
}

// CTA tile 128(j) x 128(i), 8 warps of 32x64 (wy 0..3 over j, wx 0..1 over i).
// K-chunk 64 (4 x k16). A fragments directly from reversed pair-packed h table.
__global__ __launch_bounds__(256, 2) void memint_mma(
    const float* __restrict__ fe,
    const float* __restrict__ h,
    float* __restrict__ out)
{
    extern __shared__ char smem[];
    const uint32_t sbase = smem_u32(smem);
    uint32_t* hr = (uint32_t*)smem;

    const int tid  = threadIdx.x;
    const int lane = tid & 31;
    const int wid  = tid >> 5;
    const int wy   = wid & 3;       // j strip (32)
    const int wx   = wid >> 2;      // i half (64)
    const int i0 = blockIdx.x * 128;
    const int j0 = ((int)gridDim.y - 1 - (int)blockIdx.y) * 128;   // heavy tiles first

    // hr[v] = (h[NN-1-v], h[NN-2-v]) as half2; zero-padded past the end (causal mask)
    for (int v = tid; v < HR_WORDS; v += 256) {
        float e0 = (v < NN)     ? h[NN - 1 - v] : 0.f;
        float e1 = (v + 1 < NN) ? h[NN - 2 - v] : 0.f;
        __half2 p = __floats2half2_rn(e0, e1);
        hr[v] = *(uint32_t*)&p;
    }
    __syncthreads();

    const int numT = (j0 >> 6) + 2;

    auto issue_B = [&](int t) {
        const int l0 = t * KC;
        const uint32_t bs = sbase + SM_B_OFF + (uint32_t)(t % 3) * STAGE_B;
        #pragma unroll
        for (int k = 0; k < 4; k++) {
            int m = tid + k * 256;       // 1024 16B segments
            int row = m >> 4;            // l row 0..63
            int seg = m & 15;
            cp16(bs + (uint32_t)(row * B_STRIDE + seg * 16),
                 &g_Kh[(size_t)(l0 + row) * MM + i0 + seg * 8]);
        }
        CP_COMMIT();
    };

    issue_B(0);
    if (numT > 1) issue_B(1); else CP_COMMIT();

    float c[2][8][4];
    #pragma unroll
    for (int mt = 0; mt < 2; mt++)
        #pragma unroll
        for (int nt = 0; nt < 8; nt++)
            #pragma unroll
            for (int q = 0; q < 4; q++) c[mt][nt][q] = 0.f;

    const uint32_t b_row = (uint32_t)((lane & 7) + ((lane >> 3) & 1) * 8) * B_STRIDE
                         + (uint32_t)(wx * 64 + (lane >> 4) * 8) * 2;
    // lv[mt][q] = hr[vb - mt*16 - 8 + 8q] = w[q + 2 - 2mt], w[s] = hr[vb - 24 + 8s], s=0..10
    const int wbase0 = NN - 1 - (j0 + wy * 32 + (lane >> 2)) + 2 * (lane & 3) - 24;

    for (int t = 0; t < numT; t++) {
        CP_WAIT1();
        __syncthreads();
        if (t + 2 < numT) issue_B(t + 2); else CP_COMMIT();

        uint32_t w[11];
        const int wb = wbase0 + t * KC;
        #pragma unroll
        for (int s = 0; s < 11; s++) w[s] = hr[wb + 8 * s];

        const uint32_t bs = sbase + SM_B_OFF + (uint32_t)(t % 3) * STAGE_B + b_row;
        #pragma unroll
        for (int ks = 0; ks < 4; ks++) {
            uint32_t Bf[4][4];
            #pragma unroll
            for (int np = 0; np < 4; np++)
                ldmat_x4_t(Bf[np], bs + (uint32_t)(ks * 16 * B_STRIDE + np * 32));
            #pragma unroll
            for (int mt = 0; mt < 2; mt++) {
                const int base = 2 * ks + 2 - 2 * mt;
                uint32_t a[4];
                a[0] = w[base + 1]; a[1] = w[base]; a[2] = w[base + 2]; a[3] = w[base + 1];
                #pragma unroll
                for (int nt = 0; nt < 8; nt++)
                    mma16816(c[mt][nt], a, &Bf[nt >> 1][(nt & 1) * 2]);
            }
        }
    }

    // ---- epilogue ----
    const float h0 = __ldg(&h[0]);
    float k0lo[8], k0hi[8];
    #pragma unroll
    for (int nt = 0; nt < 8; nt++) {
        const int i = i0 + wx * 64 + nt * 8 + (lane & 3) * 2;
        __half2 k0 = *(const __half2*)&g_Kh[i];
        k0lo[nt] = __low2float(k0);
        k0hi[nt] = __high2float(k0);
    }
    #pragma unroll
    for (int mt = 0; mt < 2; mt++) {
        #pragma unroll
        for (int hf = 0; hf < 2; hf++) {
            const int j = j0 + wy * 32 + mt * 16 + (lane >> 2) + hf * 8;
            const float fej = __ldg(&fe[j]);
            const float hj  = __ldg(&h[j]);
            #pragma unroll
            for (int nt = 0; nt < 8; nt++) {
                const int i = i0 + wx * 64 + nt * 8 + (lane & 3) * 2;
                const size_t gi = (size_t)j * MM + i;
                __half2 kj = *(const __half2*)&g_Kh[gi];
                const float* cc = c[mt][nt];
                float2 o;
                o.x = fej + DTC * (0.5f * k0lo[nt] * hj - 0.5f * __low2float(kj)  * h0 - cc[hf * 2 + 0]);
                o.y = fej + DTC * (0.5f * k0hi[nt] * hj - 0.5f * __high2float(kj) * h0 - cc[hf * 2 + 1]);
                *(float2*)&out[gi] = o;
            }
        }
    }
}

extern "C" void kernel_launch(void* const* d_in, const int* in_sizes, int n_in,
                              void* d_out, int out_size) {
    const float* x  = (const float*)d_in[0];
    const float* fe = (const float*)d_in[1];
    const float* h  = (const float*)d_in[2];
    float* out = (float*)d_out;

    cudaFuncSetAttribute(memint_mma, cudaFuncAttributeMaxDynamicSharedMemorySize, SMEM_TOTAL);

    exp_kernel<<<((size_t)NN * MM) / 4 / 256, 256>>>(x);

    dim3 grid(MM / 128, NN / 128);
    memint_mma<<<grid, 256, SMEM_TOTAL>>>(fe, h, out);
}

// round 10
// speedup vs baseline: 7.1843x; 1.0440x over previous
#include <cuda_runtime.h>
#include <cuda_fp16.h>
#include <cstdint>

#define NN 4096
#define MM 4096
#define DTC 0.01f

__device__ __half g_Kh[(size_t)NN * MM];

#define HR_WORDS (NN + 256)
__device__ __align__(16) uint32_t g_hr[HR_WORDS];

__global__ void exp_kernel(const float* __restrict__ x) {
    size_t p = (size_t)blockIdx.x * blockDim.x + threadIdx.x;
    float4 v = ((const float4*)x)[p];
    __half2 a = __floats2half2_rn(expf(-v.x), expf(-v.y));
    __half2 b = __floats2half2_rn(expf(-v.z), expf(-v.w));
    uint2 w;
    w.x = *(uint32_t*)&a;
    w.y = *(uint32_t*)&b;
    ((uint2*)g_Kh)[p] = w;
}

// g_hr[v] = (h[NN-1-v], h[NN-2-v]) as half2; zero-padded past the end (causal mask)
__global__ void pack_hr_kernel(const float* __restrict__ h) {
    int v = blockIdx.x * blockDim.x + threadIdx.x;
    if (v >= HR_WORDS) return;
    float e0 = (v < NN)     ? h[NN - 1 - v] : 0.f;
    float e1 = (v + 1 < NN) ? h[NN - 2 - v] : 0.f;
    __half2 p = __floats2half2_rn(e0, e1);
    g_hr[v] = *(uint32_t*)&p;
}

// ---------------- smem layout ----------------
#define SM_B_OFF (HR_WORDS * 4)        // 17408 bytes
#define B_STRIDE 272                   // 128 halfs + 8 pad
#define KC 64                          // K-chunk
#define STAGE_B  (KC * B_STRIDE)       // 17408
#define NSTAGE   3
#define SMEM_TOTAL (SM_B_OFF + NSTAGE * STAGE_B)   // 69632

__device__ __forceinline__ uint32_t smem_u32(const void* p) {
    return (uint32_t)__cvta_generic_to_shared(p);
}
__device__ __forceinline__ void cp16(uint32_t dst, const void* src) {
    asm volatile("cp.async.cg.shared.global [%0], [%1], 16;" :: "r"(dst), "l"(src) : "memory");
}
#define CP_COMMIT() asm volatile("cp.async.commit_group;" ::: "memory")
#define CP_WAIT1()  asm volatile("cp.async.wait_group 1;" ::: "memory")

__device__ __forceinline__ void ldmat_x4_t(uint32_t* r, uint32_t addr) {
    asm volatile("ldmatrix.sync.aligned.m8n8.x4.trans.shared.b16 {%0,%1,%2,%3}, [%4];"
                 : "=r"(r[0]), "=r"(r[1]), "=r"(r[2]), "=r"(r[3]) : "r"(addr));
}
__device__ __forceinline__ void mma16816(float* c, const uint32_t* a, const uint32_t* b) {
    asm volatile("mma.sync.aligned.m16n8k16.row.col.f32.f16.f16.f32 "
                 "{%0,%1,%2,%3}, {%4,%5,%6,%7}, {%8,%9}, {%0,%1,%2,%3};"
                 : "+f"(c[0]), "+f"(c[1]), "+f"(c[2]), "+f"(c[3])
                 : "r"(a[0]), "r"(a[1]), "r"(a[2]), "r"(a[3]), "r"(b[0]), "r"(b[1]));
}

// CTA tile 128(j) x 128(i), 8 warps of 64(j) x 32(i): wy 0..1, wx 0..3.
// K-chunk 64 (4 x k16). A fragments directly from reversed pair-packed h table.
__global__ __launch_bounds__(256, 2) void memint_mma(
    const float* __restrict__ fe,
    const float* __restrict__ h,
    float* __restrict__ out)
{
    extern __shared__ char smem[];
    const uint32_t sbase = smem_u32(smem);
    uint32_t* hr = (uint32_t*)smem;

    const int tid  = threadIdx.x;
    const int lane = tid & 31;
    const int wid  = tid >> 5;
    const int wy   = wid & 1;       // j half (64)
    const int wx   = wid >> 1;      // i quarter (32)
    const int i0 = blockIdx.x * 128;
    const int j0 = ((int)gridDim.y - 1 - (int)blockIdx.y) * 128;   // heavy tiles first

    const int numT = (j0 >> 6) + 2;

    auto issue_B = [&](int t) {
        const int l0 = t * KC;
        const uint32_t bs = sbase + SM_B_OFF + (uint32_t)(t % 3) * STAGE_B;
        #pragma unroll
        for (int k = 0; k < 4; k++) {
            int m = tid + k * 256;       // 1024 16B segments
            int row = m >> 4;            // l row 0..63
            int seg = m & 15;
            cp16(bs + (uint32_t)(row * B_STRIDE + seg * 16),
                 &g_Kh[(size_t)(l0 + row) * MM + i0 + seg * 8]);
        }
        CP_COMMIT();
    };

    // prologue: hr table via cp.async (1088 16B segs), then B0, B1
    #pragma unroll
    for (int k = 0; k < 5; k++) {
        int m = tid + k * 256;
        if (m < HR_WORDS / 4) cp16(sbase + (uint32_t)m * 16, &g_hr[m * 4]);
    }
    CP_COMMIT();
    issue_B(0);
    if (numT > 1) issue_B(1); else CP_COMMIT();

    float c[4][4][4];
    #pragma unroll
    for (int mt = 0; mt < 4; mt++)
        #pragma unroll
        for (int nt = 0; nt < 4; nt++)
            #pragma unroll
            for (int q = 0; q < 4; q++) c[mt][nt][q] = 0.f;

    const uint32_t b_row = (uint32_t)((lane & 7) + ((lane >> 3) & 1) * 8) * B_STRIDE
                         + (uint32_t)(wx * 32 + (lane >> 4) * 8) * 2;
    // lv[mt][q] = hr[vb - mt*16 - 8 + 8q] = w[q + 6 - 2mt], w[s] = hr[vb - 56 + 8s], s=0..14
    const int wbase0 = NN - 1 - (j0 + wy * 64 + (lane >> 2)) + 2 * (lane & 3) - 56;

    for (int t = 0; t < numT; t++) {
        CP_WAIT1();
        __syncthreads();
        if (t + 2 < numT) issue_B(t + 2); else CP_COMMIT();

        uint32_t w[15];
        const int wb = wbase0 + t * KC;
        #pragma unroll
        for (int s = 0; s < 15; s++) w[s] = hr[wb + 8 * s];

        const uint32_t bs = sbase + SM_B_OFF + (uint32_t)(t % 3) * STAGE_B + b_row;
        #pragma unroll
        for (int ks = 0; ks < 4; ks++) {
            uint32_t Bf[2][4];
            #pragma unroll
            for (int np = 0; np < 2; np++)
                ldmat_x4_t(Bf[np], bs + (uint32_t)(ks * 16 * B_STRIDE + np * 32));
            #pragma unroll
            for (int mt = 0; mt < 4; mt++) {
                const int base = 2 * ks + 6 - 2 * mt;
                uint32_t a[4];
                a[0] = w[base + 1]; a[1] = w[base]; a[2] = w[base + 2]; a[3] = w[base + 1];
                #pragma unroll
                for (int nt = 0; nt < 4; nt++)
                    mma16816(c[mt][nt], a, &Bf[nt >> 1][(nt & 1) * 2]);
            }
        }
    }

    // ---- epilogue ----
    const float h0 = __ldg(&h[0]);
    float k0lo[4], k0hi[4];
    #pragma unroll
    for (int nt = 0; nt < 4; nt++) {
        const int i = i0 + wx * 32 + nt * 8 + (lane & 3) * 2;
        __half2 k0 = *(const __half2*)&g_Kh[i];
        k0lo[nt] = __low2float(k0);
        k0hi[nt] = __high2float(k0);
    }
    #pragma unroll
    for (int mt = 0; mt < 4; mt++) {
        #pragma unroll
        for (int hf = 0; hf < 2; hf++) {
            const int j = j0 + wy * 64 + mt * 16 + (lane >> 2) + hf * 8;
            const float fej = __ldg(&fe[j]);
            const float hj  = __ldg(&h[j]);
            #pragma unroll
            for (int nt = 0; nt < 4; nt++) {
                const int i = i0 + wx * 32 + nt * 8 + (lane & 3) * 2;
                const size_t gi = (size_t)j * MM + i;
                __half2 kj = *(const __half2*)&g_Kh[gi];
                const float* cc = c[mt][nt];
                float2 o;
                o.x = fej + DTC * (0.5f * k0lo[nt] * hj - 0.5f * __low2float(kj)  * h0 - cc[hf * 2 + 0]);
                o.y = fej + DTC * (0.5f * k0hi[nt] * hj - 0.5f * __high2float(kj) * h0 - cc[hf * 2 + 1]);
                *(float2*)&out[gi] = o;
            }
        }
    }
}

extern "C" void kernel_launch(void* const* d_in, const int* in_sizes, int n_in,
                              void* d_out, int out_size) {
    const float* x  = (const float*)d_in[0];
    const float* fe = (const float*)d_in[1];
    const float* h  = (const float*)d_in[2];
    float* out = (float*)d_out;

    cudaFuncSetAttribute(memint_mma, cudaFuncAttributeMaxDynamicSharedMemorySize, SMEM_TOTAL);

    exp_kernel<<<((size_t)NN * MM) / 4 / 256, 256>>>(x);
    pack_hr_kernel<<<(HR_WORDS + 255) / 256, 256>>>(h);

    dim3 grid(MM / 128, NN / 128);
    memint_mma<<<grid, 256, SMEM_TOTAL>>>(fe, h, out);
}